// round 13
// baseline (speedup 1.0000x reference)
#include <cuda_runtime.h>
#include <math.h>

#define Nx   256
#define BN   2048      // 8*256

// ---------------- scratch ----------------
__device__ float g_A [BN*128];   // h @ Wm1[0:128]
__device__ float g_Bm[BN*128];   // h @ Wm1[128:256]
__device__ float g_as[BN];
__device__ float g_bs[BN];
__device__ float g_S0[BN*128];   // partial S, j in [0,128)
__device__ float g_S1[BN*128];   // partial S, j in [128,256)
__device__ float g_c [BN];       // sum_j w_ij
__device__ float g_M [128*128];  // Wm2 @ Wu_bot
__device__ float g_vb[128];      // bm2 @ Wu_bot + bu

typedef unsigned long long u64;

__device__ __forceinline__ u64 add2v(u64 a, u64 b) {
    u64 r; asm("add.rn.f32x2 %0, %1, %2;" : "=l"(r) : "l"(a), "l"(b));
    return r;
}
__device__ __forceinline__ u64 fma2v(u64 a, u64 b, u64 c) {
    u64 r; asm("fma.rn.f32x2 %0, %1, %2, %3;" : "=l"(r) : "l"(a), "l"(b), "l"(c));
    return r;
}
__device__ __forceinline__ float2 unpk(u64 v) {
    unsigned lo, hi;
    asm("mov.b64 {%0, %1}, %2;" : "=r"(lo), "=r"(hi) : "l"(v));
    return make_float2(__uint_as_float(lo), __uint_as_float(hi));
}
__device__ __forceinline__ u64 pack2(float x, float y) {
    u64 r;
    asm("mov.b64 %0, {%1, %2};" : "=l"(r)
        : "r"(__float_as_uint(x)), "r"(__float_as_uint(y)));
    return r;
}
__device__ __forceinline__ u64 relu2(u64 v) {
    float2 f = unpk(v);
    return pack2(fmaxf(f.x, 0.f), fmaxf(f.y, 0.f));
}

// =======================================================================
// Stage 1 (R2-proven, verbatim): grid 141, block 256
// =======================================================================
__global__ void __launch_bounds__(256) k_stage1(
    const float* __restrict__ h,   const float* __restrict__ Wm1,
    const float* __restrict__ Wa,  const float* __restrict__ Wm2,
    const float* __restrict__ bm2, const float* __restrict__ Wu,
    const float* __restrict__ bu)
{
    const int bid = blockIdx.x;
    const int t   = threadIdx.x;

    if (bid < 132) {
        __shared__ float As[32][68];
        __shared__ float Ws[32][68];
        const float *A, *W;
        float* dst;
        int row0, col0;
        if (bid < 128) {
            int mt = bid >> 2, nt = bid & 3;
            row0 = mt * 64;
            A = h;
            W = Wm1 + (nt >= 2 ? 128*128 : 0);
            col0 = (nt & 1) * 64;
            dst = (nt >= 2) ? g_Bm : g_A;
        } else {
            int bb = bid - 128;
            row0 = (bb >> 1) * 64;
            A = Wm2;
            W = Wu + 128*128;
            col0 = (bb & 1) * 64;
            dst = g_M;
        }
        const int ty = t >> 4, tx = t & 15;
        float acc[4][4];
#pragma unroll
        for (int r = 0; r < 4; r++)
#pragma unroll
            for (int c = 0; c < 4; c++) acc[r][c] = 0.f;

        for (int k0 = 0; k0 < 128; k0 += 32) {
#pragma unroll
            for (int n = 0; n < 2; n++) {
                int l  = t + n*256;
                int r  = l >> 3;
                int kq = (l & 7) * 4;
                float4 v = *(const float4*)&A[(row0 + r)*128 + k0 + kq];
                As[kq+0][r] = v.x; As[kq+1][r] = v.y;
                As[kq+2][r] = v.z; As[kq+3][r] = v.w;
            }
#pragma unroll
            for (int n = 0; n < 2; n++) {
                int l  = t + n*256;
                int wk = l >> 4;
                int wn = (l & 15) * 4;
                *(float4*)&Ws[wk][wn] =
                    *(const float4*)&W[(k0 + wk)*128 + col0 + wn];
            }
            __syncthreads();
#pragma unroll
            for (int kk = 0; kk < 32; kk++) {
                float4 a4 = *(const float4*)&As[kk][ty*4];
                float4 b4 = *(const float4*)&Ws[kk][tx*4];
                acc[0][0] = fmaf(a4.x, b4.x, acc[0][0]);
                acc[0][1] = fmaf(a4.x, b4.y, acc[0][1]);
                acc[0][2] = fmaf(a4.x, b4.z, acc[0][2]);
                acc[0][3] = fmaf(a4.x, b4.w, acc[0][3]);
                acc[1][0] = fmaf(a4.y, b4.x, acc[1][0]);
                acc[1][1] = fmaf(a4.y, b4.y, acc[1][1]);
                acc[1][2] = fmaf(a4.y, b4.z, acc[1][2]);
                acc[1][3] = fmaf(a4.y, b4.w, acc[1][3]);
                acc[2][0] = fmaf(a4.z, b4.x, acc[2][0]);
                acc[2][1] = fmaf(a4.z, b4.y, acc[2][1]);
                acc[2][2] = fmaf(a4.z, b4.z, acc[2][2]);
                acc[2][3] = fmaf(a4.z, b4.w, acc[2][3]);
                acc[3][0] = fmaf(a4.w, b4.x, acc[3][0]);
                acc[3][1] = fmaf(a4.w, b4.y, acc[3][1]);
                acc[3][2] = fmaf(a4.w, b4.z, acc[3][2]);
                acc[3][3] = fmaf(a4.w, b4.w, acc[3][3]);
            }
            __syncthreads();
        }
#pragma unroll
        for (int r = 0; r < 4; r++)
            *(float4*)&dst[(row0 + ty*4 + r)*128 + col0 + tx*4] =
                make_float4(acc[r][0], acc[r][1], acc[r][2], acc[r][3]);

    } else if (bid < 140) {
        __shared__ __align__(16) float was[272];
        for (int k = t; k < 257; k += 256) was[k] = Wa[k];
        __syncthreads();
        const int wrp = t >> 5, lane = t & 31;
        const int rowbase = (bid - 132) * 256 + wrp * 32;
        float4 wa1 = *(const float4*)&was[lane*4];
        float4 wa2 = *(const float4*)&was[128 + lane*4];
        for (int rr = 0; rr < 32; rr++) {
            int row = rowbase + rr;
            float4 hv = *(const float4*)&h[row*128 + lane*4];
            float sa = hv.x*wa1.x + hv.y*wa1.y + hv.z*wa1.z + hv.w*wa1.w;
            float sb = hv.x*wa2.x + hv.y*wa2.y + hv.z*wa2.z + hv.w*wa2.w;
#pragma unroll
            for (int o = 16; o; o >>= 1) {
                sa += __shfl_xor_sync(0xffffffffu, sa, o);
                sb += __shfl_xor_sync(0xffffffffu, sb, o);
            }
            if (lane == 0) { g_as[row] = sa; g_bs[row] = sb; }
        }
    } else {
        if (t < 128) {
            float acc = bu[t];
#pragma unroll 8
            for (int k = 0; k < 128; k++)
                acc = fmaf(bm2[k], Wu[(128 + k)*128 + t], acc);
            g_vb[t] = acc;
        }
    }
}

// =======================================================================
// k_pair: j-split, 2 blocks/SM, NO spills.
// grid (16, 2, 8) = (i-tile, j-half, batch), block 512.
// thread = (cp 0..63, qq 0..3, ih 0..1): 8 i's, j = jj*4+qq (local half)
// smem: Bsh 64KB | dwsh 32KB | Ash 8KB | bssh 1KB = 107520B -> 2/SM
// =======================================================================
#define PAIR_SMEM ((16384 + 8192 + 2048 + 256) * 4)

__global__ void __launch_bounds__(512, 2) k_pair(
    const float* __restrict__ dist, const int* __restrict__ adj,
    const float* __restrict__ Wm1,  const float* __restrict__ bm1,
    const float* __restrict__ Wa,   const float* __restrict__ ba)
{
    extern __shared__ float sm[];
    float*  Bsh  = sm;                       // [128][128] j-half  64KB
    float4* dwsh = (float4*)(sm + 16384);    // [16][128] {d,d,w,w} 32KB
    float*  Ash  = sm + 16384 + 8192;        // [16][128] A + bm1    8KB
    float*  bssh = Ash + 2048;               // 256                  1KB

    const int t    = threadIdx.x;
    const int i0   = blockIdx.x * 16;
    const int half = blockIdx.y;
    const int b    = blockIdx.z;
    const int lane = t & 31, wrp = t >> 5;

    // ---- fills
    {
        const float4* src =
            (const float4*)(g_Bm + ((size_t)b*Nx + half*128)*128);
        float4* d4 = (float4*)Bsh;
#pragma unroll
        for (int k = 0; k < 8; k++) d4[t + k*512] = src[t + k*512];
    }
#pragma unroll
    for (int k = 0; k < 4; k++) {
        int idx = t + k*512;
        Ash[idx] = g_A[(size_t)(b*Nx + i0)*128 + idx] + bm1[idx & 127];
    }
    if (t < 256) bssh[t] = g_bs[b*Nx + t];
    __syncthreads();

    // ---- phase-2 register preload (Ash is stable from here on)
    const int cp = t & 63, qq = (t >> 6) & 3, ih = t >> 8;
    const u64 wd2 = *(const u64*)&Wm1[256*128 + cp*2];
    u64 a2[8], acc2[8];
#pragma unroll
    for (int i8 = 0; i8 < 8; i8++) {
        a2[i8]   = *(const u64*)&Ash[(ih*8 + i8)*128 + cp*2];
        acc2[i8] = 0ull;
    }

    // ---- phase 1: warp wrp -> i = i0 + wrp; full softmax, store own half
    {
        const float wa_d = Wa[256];
        const int ig = b*Nx + i0 + wrp;
        const float a_i = g_as[ig] + ba[0];
        float l[8], dv[8]; int mk[8];
#pragma unroll
        for (int jj = 0; jj < 8; jj++) {
            int j = jj*32 + lane;
            float d = dist[(size_t)ig*Nx + j];
            int   m = adj [(size_t)ig*Nx + j];
            float x = fmaf(d, wa_d, a_i + bssh[j]);
            x = (x >= 0.f) ? x : 0.2f * x;
            l[jj] = m ? x : -1e9f;
            dv[jj] = d; mk[jj] = m;
        }
        float mx = l[0];
#pragma unroll
        for (int jj = 1; jj < 8; jj++) mx = fmaxf(mx, l[jj]);
#pragma unroll
        for (int o = 16; o; o >>= 1) mx = fmaxf(mx, __shfl_xor_sync(0xffffffffu, mx, o));
        float sum = 0.f, cs = 0.f;
#pragma unroll
        for (int jj = 0; jj < 8; jj++) {
            float e = expf(l[jj] - mx);
            l[jj] = e; sum += e;
            cs += mk[jj] ? e : 0.f;
        }
#pragma unroll
        for (int o = 16; o; o >>= 1) {
            sum += __shfl_xor_sync(0xffffffffu, sum, o);
            cs  += __shfl_xor_sync(0xffffffffu, cs,  o);
        }
        const float inv = 1.f / sum;
#pragma unroll
        for (int jjl = 0; jjl < 4; jjl++) {
            int jj = half*4 + jjl;
            float w = mk[jj] ? l[jj]*inv : 0.f;
            dwsh[wrp*128 + jjl*32 + lane] =
                make_float4(dv[jj], dv[jj], w, w);
        }
        if (half == 0 && lane == 0) g_c[ig] = cs * inv;
    }
    __syncthreads();

    // ---- phase 2: 32 jj x 8 i chains per thread
    const ulonglong2* dwp = (const ulonglong2*)dwsh;
#pragma unroll 1
    for (int jj = 0; jj < 32; jj++) {
        const int j = jj*4 + qq;
        u64 b2 = *(const u64*)&Bsh[j*128 + cp*2];
#pragma unroll
        for (int i8 = 0; i8 < 8; i8++) {
            ulonglong2 dw = dwp[(ih*8 + i8)*128 + j];   // bcast LDS.128
            u64 x = fma2v(dw.x, wd2, add2v(a2[i8], b2));
            acc2[i8] = fma2v(dw.y, relu2(x), acc2[i8]);
        }
    }
    __syncthreads();   // Bsh/dwsh reads done

    // ---- reduce over 4 qq partials via overlay on Bsh
    u64* part = (u64*)Bsh;   // [16][4][64] = 32KB
#pragma unroll
    for (int i8 = 0; i8 < 8; i8++)
        part[((ih*8 + i8)*4 + qq)*64 + cp] = acc2[i8];
    __syncthreads();

    float* g_Sp = half ? g_S1 : g_S0;
#pragma unroll
    for (int rep = 0; rep < 2; rep++) {
        int idx = t + rep*512;          // 0..1023
        int i = idx >> 6, c2 = idx & 63;
        float2 s = make_float2(0.f, 0.f);
#pragma unroll
        for (int r = 0; r < 4; r++) {
            float2 v = unpk(part[(i*4 + r)*64 + c2]);
            s.x += v.x; s.y += v.y;
        }
        *(float2*)&g_Sp[(size_t)(b*Nx + i0 + i)*128 + c2*2] = s;
    }
}

// =======================================================================
// k_out (R2 structure; S = S0 + S1): grid (64,2), block 256
// =======================================================================
__global__ void __launch_bounds__(256) k_out(
    const float* __restrict__ h, const float* __restrict__ Wu,
    float* __restrict__ out)
{
    __shared__ float As[32][36];
    __shared__ float Ws[32][68];
    const int t = threadIdx.x;
    const int row0 = blockIdx.x * 32, col0 = blockIdx.y * 64;
    const int ty = t >> 4, tx = t & 15;
    float acc[2][4];
#pragma unroll
    for (int r = 0; r < 2; r++)
#pragma unroll
        for (int c = 0; c < 4; c++) acc[r][c] = 0.f;

    for (int k0 = 0; k0 < 256; k0 += 32) {
        {
            int r  = t >> 3;
            int kq = (t & 7) * 4;
            int kg = k0 + kq;
            float4 v;
            if (kg < 128) {
                v = *(const float4*)&h[(row0 + r)*128 + kg];
            } else {
                float4 v0 = *(const float4*)&g_S0[(size_t)(row0 + r)*128 + kg - 128];
                float4 v1 = *(const float4*)&g_S1[(size_t)(row0 + r)*128 + kg - 128];
                v = make_float4(v0.x + v1.x, v0.y + v1.y,
                                v0.z + v1.z, v0.w + v1.w);
            }
            As[kq+0][r] = v.x; As[kq+1][r] = v.y;
            As[kq+2][r] = v.z; As[kq+3][r] = v.w;
        }
#pragma unroll
        for (int n = 0; n < 2; n++) {
            int l  = t + n*256;
            int wk = l >> 4;
            int wn = (l & 15) * 4;
            int kg = k0 + wk;
            const float* src = (kg < 128) ? &Wu [kg*128 + col0 + wn]
                                          : &g_M[(kg - 128)*128 + col0 + wn];
            *(float4*)&Ws[wk][wn] = *(const float4*)src;
        }
        __syncthreads();
#pragma unroll
        for (int kk = 0; kk < 32; kk++) {
            float2 a2 = *(const float2*)&As[kk][ty*2];
            float4 b4 = *(const float4*)&Ws[kk][tx*4];
            acc[0][0] = fmaf(a2.x, b4.x, acc[0][0]);
            acc[0][1] = fmaf(a2.x, b4.y, acc[0][1]);
            acc[0][2] = fmaf(a2.x, b4.z, acc[0][2]);
            acc[0][3] = fmaf(a2.x, b4.w, acc[0][3]);
            acc[1][0] = fmaf(a2.y, b4.x, acc[1][0]);
            acc[1][1] = fmaf(a2.y, b4.y, acc[1][1]);
            acc[1][2] = fmaf(a2.y, b4.z, acc[1][2]);
            acc[1][3] = fmaf(a2.y, b4.w, acc[1][3]);
        }
        __syncthreads();
    }

    float4 vb4 = *(const float4*)&g_vb[col0 + tx*4];
#pragma unroll
    for (int r = 0; r < 2; r++) {
        int row = row0 + ty*2 + r;
        float cr = g_c[row];
        float4 v;
        v.x = fmaxf(fmaf(cr, vb4.x, acc[r][0]), 0.f);
        v.y = fmaxf(fmaf(cr, vb4.y, acc[r][1]), 0.f);
        v.z = fmaxf(fmaf(cr, vb4.z, acc[r][2]), 0.f);
        v.w = fmaxf(fmaf(cr, vb4.w, acc[r][3]), 0.f);
        *(float4*)&out[row*128 + col0 + tx*4] = v;
    }
}

// =======================================================================
extern "C" void kernel_launch(void* const* d_in, const int* in_sizes, int n_in,
                              void* d_out, int out_size)
{
    const float* h    = (const float*)d_in[0];
    const int*   adj  = (const int*)  d_in[1];
    const float* dist = (const float*)d_in[2];
    const float* Wm1  = (const float*)d_in[3];
    const float* bm1  = (const float*)d_in[4];
    const float* Wm2  = (const float*)d_in[5];
    const float* bm2  = (const float*)d_in[6];
    const float* Wa   = (const float*)d_in[7];
    const float* ba   = (const float*)d_in[8];
    const float* Wu   = (const float*)d_in[9];
    const float* bu   = (const float*)d_in[10];
    float* out = (float*)d_out;

    cudaFuncSetAttribute(k_pair, cudaFuncAttributeMaxDynamicSharedMemorySize,
                         PAIR_SMEM);

    k_stage1<<<141, 256>>>(h, Wm1, Wa, Wm2, bm2, Wu, bu);
    k_pair  <<<dim3(16, 2, 8), 512, PAIR_SMEM>>>(dist, adj, Wm1, bm1, Wa, ba);
    k_out   <<<dim3(64, 2), 256>>>(h, Wu, out);
}

// round 14
// speedup vs baseline: 1.0608x; 1.0608x over previous
#include <cuda_runtime.h>
#include <math.h>

#define Nx   256
#define BN   2048      // 8*256

// ---------------- scratch ----------------
__device__ float g_A [BN*128];   // h @ Wm1[0:128]
__device__ float g_Bm[BN*128];   // h @ Wm1[128:256]
__device__ float g_as[BN];
__device__ float g_bs[BN];
__device__ float g_S [BN*128];   // sum_j w_ij * relu(pre_ij)
__device__ float g_c [BN];       // sum_j w_ij
__device__ float g_M [128*128];  // Wm2 @ Wu_bot
__device__ float g_vb[128];      // bm2 @ Wu_bot + bu

typedef unsigned long long u64;

__device__ __forceinline__ u64 dup2(float a) {
    u64 r; unsigned au = __float_as_uint(a);
    asm("mov.b64 %0, {%1, %1};" : "=l"(r) : "r"(au));
    return r;
}
__device__ __forceinline__ u64 add2v(u64 a, u64 b) {
    u64 r; asm("add.rn.f32x2 %0, %1, %2;" : "=l"(r) : "l"(a), "l"(b));
    return r;
}
__device__ __forceinline__ u64 fma2v(u64 a, u64 b, u64 c) {
    u64 r; asm("fma.rn.f32x2 %0, %1, %2, %3;" : "=l"(r) : "l"(a), "l"(b), "l"(c));
    return r;
}
__device__ __forceinline__ float2 unpk(u64 v) {
    unsigned lo, hi;
    asm("mov.b64 {%0, %1}, %2;" : "=r"(lo), "=r"(hi) : "l"(v));
    return make_float2(__uint_as_float(lo), __uint_as_float(hi));
}
__device__ __forceinline__ u64 pack2(float x, float y) {
    u64 r;
    asm("mov.b64 %0, {%1, %2};" : "=l"(r)
        : "r"(__float_as_uint(x)), "r"(__float_as_uint(y)));
    return r;
}
__device__ __forceinline__ u64 relu2(u64 v) {
    float2 f = unpk(v);
    return pack2(fmaxf(f.x, 0.f), fmaxf(f.y, 0.f));
}

// =======================================================================
// Stage 1 (R2-proven, verbatim): grid 141, block 256
// =======================================================================
__global__ void __launch_bounds__(256) k_stage1(
    const float* __restrict__ h,   const float* __restrict__ Wm1,
    const float* __restrict__ Wa,  const float* __restrict__ Wm2,
    const float* __restrict__ bm2, const float* __restrict__ Wu,
    const float* __restrict__ bu)
{
    const int bid = blockIdx.x;
    const int t   = threadIdx.x;

    if (bid < 132) {
        __shared__ float As[32][68];
        __shared__ float Ws[32][68];
        const float *A, *W;
        float* dst;
        int row0, col0;
        if (bid < 128) {
            int mt = bid >> 2, nt = bid & 3;
            row0 = mt * 64;
            A = h;
            W = Wm1 + (nt >= 2 ? 128*128 : 0);
            col0 = (nt & 1) * 64;
            dst = (nt >= 2) ? g_Bm : g_A;
        } else {
            int bb = bid - 128;
            row0 = (bb >> 1) * 64;
            A = Wm2;
            W = Wu + 128*128;
            col0 = (bb & 1) * 64;
            dst = g_M;
        }
        const int ty = t >> 4, tx = t & 15;
        float acc[4][4];
#pragma unroll
        for (int r = 0; r < 4; r++)
#pragma unroll
            for (int c = 0; c < 4; c++) acc[r][c] = 0.f;

        for (int k0 = 0; k0 < 128; k0 += 32) {
#pragma unroll
            for (int n = 0; n < 2; n++) {
                int l  = t + n*256;
                int r  = l >> 3;
                int kq = (l & 7) * 4;
                float4 v = *(const float4*)&A[(row0 + r)*128 + k0 + kq];
                As[kq+0][r] = v.x; As[kq+1][r] = v.y;
                As[kq+2][r] = v.z; As[kq+3][r] = v.w;
            }
#pragma unroll
            for (int n = 0; n < 2; n++) {
                int l  = t + n*256;
                int wk = l >> 4;
                int wn = (l & 15) * 4;
                *(float4*)&Ws[wk][wn] =
                    *(const float4*)&W[(k0 + wk)*128 + col0 + wn];
            }
            __syncthreads();
#pragma unroll
            for (int kk = 0; kk < 32; kk++) {
                float4 a4 = *(const float4*)&As[kk][ty*4];
                float4 b4 = *(const float4*)&Ws[kk][tx*4];
                acc[0][0] = fmaf(a4.x, b4.x, acc[0][0]);
                acc[0][1] = fmaf(a4.x, b4.y, acc[0][1]);
                acc[0][2] = fmaf(a4.x, b4.z, acc[0][2]);
                acc[0][3] = fmaf(a4.x, b4.w, acc[0][3]);
                acc[1][0] = fmaf(a4.y, b4.x, acc[1][0]);
                acc[1][1] = fmaf(a4.y, b4.y, acc[1][1]);
                acc[1][2] = fmaf(a4.y, b4.z, acc[1][2]);
                acc[1][3] = fmaf(a4.y, b4.w, acc[1][3]);
                acc[2][0] = fmaf(a4.z, b4.x, acc[2][0]);
                acc[2][1] = fmaf(a4.z, b4.y, acc[2][1]);
                acc[2][2] = fmaf(a4.z, b4.z, acc[2][2]);
                acc[2][3] = fmaf(a4.z, b4.w, acc[2][3]);
                acc[3][0] = fmaf(a4.w, b4.x, acc[3][0]);
                acc[3][1] = fmaf(a4.w, b4.y, acc[3][1]);
                acc[3][2] = fmaf(a4.w, b4.z, acc[3][2]);
                acc[3][3] = fmaf(a4.w, b4.w, acc[3][3]);
            }
            __syncthreads();
        }
#pragma unroll
        for (int r = 0; r < 4; r++)
            *(float4*)&dst[(row0 + ty*4 + r)*128 + col0 + tx*4] =
                make_float4(acc[r][0], acc[r][1], acc[r][2], acc[r][3]);

    } else if (bid < 140) {
        __shared__ __align__(16) float was[272];
        for (int k = t; k < 257; k += 256) was[k] = Wa[k];
        __syncthreads();
        const int wrp = t >> 5, lane = t & 31;
        const int rowbase = (bid - 132) * 256 + wrp * 32;
        float4 wa1 = *(const float4*)&was[lane*4];
        float4 wa2 = *(const float4*)&was[128 + lane*4];
        for (int rr = 0; rr < 32; rr++) {
            int row = rowbase + rr;
            float4 hv = *(const float4*)&h[row*128 + lane*4];
            float sa = hv.x*wa1.x + hv.y*wa1.y + hv.z*wa1.z + hv.w*wa1.w;
            float sb = hv.x*wa2.x + hv.y*wa2.y + hv.z*wa2.z + hv.w*wa2.w;
#pragma unroll
            for (int o = 16; o; o >>= 1) {
                sa += __shfl_xor_sync(0xffffffffu, sa, o);
                sb += __shfl_xor_sync(0xffffffffu, sb, o);
            }
            if (lane == 0) { g_as[row] = sa; g_bs[row] = sb; }
        }
    } else {
        if (t < 128) {
            float acc = bu[t];
#pragma unroll 8
            for (int k = 0; k < 128; k++)
                acc = fmaf(bm2[k], Wu[(128 + k)*128 + t], acc);
            g_vb[t] = acc;
        }
    }
}

// =======================================================================
// k_pair: R2 skeleton + ADJACENCY COMPACTION (halves phase-2 fma work)
// grid (16,8), block 512, dyn smem 222272
// smem: Bsh 128KB | recsh {dd,ww} 64KB | jsh 16KB | Ash 8KB | bssh 1KB | nnz
// =======================================================================
#define PAIR_SMEM ((32768 + 16384 + 4096 + 2048 + 256 + 16) * 4)

__global__ void __launch_bounds__(512, 1) k_pair(
    const float* __restrict__ dist, const int* __restrict__ adj,
    const float* __restrict__ Wm1,  const float* __restrict__ bm1,
    const float* __restrict__ Wa,   const float* __restrict__ ba)
{
    extern __shared__ float sm[];
    float*      Bsh   = sm;                              // [256][128]
    ulonglong2* recsh = (ulonglong2*)(sm + 32768);       // [16][256] {dd,ww}
    int*        jsh   = (int*)(sm + 32768 + 16384);      // [16][256]
    float*      Ash   = sm + 32768 + 16384 + 4096;       // [16][128] A+bm1
    float*      bssh  = Ash + 2048;                      // 256
    int*        nnzsh = (int*)(bssh + 256);              // 16

    const int t = threadIdx.x;
    const int b = blockIdx.y, i0 = blockIdx.x * 16;
    const int lane = t & 31, wrp = t >> 5;

    // ---- fills
    {
        const float4* src = (const float4*)(g_Bm + (size_t)b*Nx*128);
        float4* d4 = (float4*)Bsh;
#pragma unroll
        for (int k = 0; k < 16; k++) d4[t + k*512] = src[t + k*512];
    }
#pragma unroll
    for (int k = 0; k < 4; k++) {
        int idx = t + k*512;
        Ash[idx] = g_A[(size_t)(b*Nx + i0)*128 + idx] + bm1[idx & 127];
    }
    if (t < 256) bssh[t] = g_bs[b*Nx + t];
    __syncthreads();

    // ---- phase 1: warp wrp -> i = i0 + wrp; softmax + ballot compaction
    {
        const float wa_d = Wa[256];
        const int ig = b*Nx + i0 + wrp;
        const float a_i = g_as[ig] + ba[0];
        float l[8], dv[8]; int mk[8];
#pragma unroll
        for (int jj = 0; jj < 8; jj++) {
            int j = jj*32 + lane;
            float d = dist[(size_t)ig*Nx + j];
            int   m = adj [(size_t)ig*Nx + j];
            float x = fmaf(d, wa_d, a_i + bssh[j]);
            x = (x >= 0.f) ? x : 0.2f * x;
            l[jj] = m ? x : -1e9f;
            dv[jj] = d; mk[jj] = m;
        }
        float mx = l[0];
#pragma unroll
        for (int jj = 1; jj < 8; jj++) mx = fmaxf(mx, l[jj]);
#pragma unroll
        for (int o = 16; o; o >>= 1) mx = fmaxf(mx, __shfl_xor_sync(0xffffffffu, mx, o));
        float sum = 0.f, cs = 0.f;
#pragma unroll
        for (int jj = 0; jj < 8; jj++) {
            float e = expf(l[jj] - mx);
            l[jj] = e; sum += e;
            cs += mk[jj] ? e : 0.f;
        }
#pragma unroll
        for (int o = 16; o; o >>= 1) {
            sum += __shfl_xor_sync(0xffffffffu, sum, o);
            cs  += __shfl_xor_sync(0xffffffffu, cs,  o);
        }
        const float inv = 1.f / sum;
        int nbase = 0;
#pragma unroll
        for (int jj = 0; jj < 8; jj++) {
            unsigned bal = __ballot_sync(0xffffffffu, mk[jj] != 0);
            if (mk[jj]) {
                int pos = nbase + __popc(bal & ((1u << lane) - 1u));
                ulonglong2 rec;
                rec.x = dup2(dv[jj]);
                rec.y = dup2(l[jj] * inv);
                recsh[wrp*256 + pos] = rec;
                jsh  [wrp*256 + pos] = jj*32 + lane;
            }
            nbase += __popc(bal);
        }
        if (lane == 0) { nnzsh[wrp] = nbase; g_c[ig] = cs * inv; }
    }
    __syncthreads();

    // ---- phase 2: thread (cp 0..63, q 0..7); compacted j-lists per i
    const int cp = t & 63, q = t >> 6;
    const u64 wd2 = *(const u64*)&Wm1[256*128 + cp*2];
    u64 acc2[16];
#pragma unroll
    for (int i = 0; i < 16; i++) acc2[i] = 0ull;

#pragma unroll
    for (int i = 0; i < 16; i++) {
        const u64 av = *(const u64*)&Ash[i*128 + cp*2];   // bcast LDS.64
        const int n = nnzsh[i];
        const ulonglong2* rp = recsh + i*256;
        const int*        jp = jsh   + i*256;
#pragma unroll 2
        for (int s = q; s < n; s += 8) {
            int j = jp[s];                    // bcast LDS.32
            ulonglong2 rec = rp[s];           // bcast LDS.128 {dd, ww}
            u64 b2 = *(const u64*)&Bsh[j*128 + cp*2];
            u64 x = fma2v(rec.x, wd2, add2v(av, b2));
            acc2[i] = fma2v(rec.y, relu2(x), acc2[i]);
        }
    }
    __syncthreads();   // Bsh/recsh/jsh reads done

    // ---- reduce over q (8 partials) via overlay on recsh (64KB)
    u64* part = (u64*)recsh;   // [16][8][64]
#pragma unroll
    for (int i = 0; i < 16; i++) part[(i*8 + q)*64 + cp] = acc2[i];
    __syncthreads();
#pragma unroll
    for (int rep = 0; rep < 2; rep++) {
        int it = t + rep*512;
        int i = it >> 6, cpp = it & 63;
        float2 s = make_float2(0.f, 0.f);
#pragma unroll
        for (int qq = 0; qq < 8; qq++) {
            float2 v = unpk(part[(i*8 + qq)*64 + cpp]);
            s.x += v.x; s.y += v.y;
        }
        *(float2*)&g_S[(size_t)(b*Nx + i0 + i)*128 + cpp*2] = s;
    }
}

// =======================================================================
// k_out (R2-proven, verbatim): out = relu( [h|S] @ [Wu_top;M] + c*vb )
// grid (64,2), block 256
// =======================================================================
__global__ void __launch_bounds__(256) k_out(
    const float* __restrict__ h, const float* __restrict__ Wu,
    float* __restrict__ out)
{
    __shared__ float As[32][36];
    __shared__ float Ws[32][68];
    const int t = threadIdx.x;
    const int row0 = blockIdx.x * 32, col0 = blockIdx.y * 64;
    const int ty = t >> 4, tx = t & 15;
    float acc[2][4];
#pragma unroll
    for (int r = 0; r < 2; r++)
#pragma unroll
        for (int c = 0; c < 4; c++) acc[r][c] = 0.f;

    for (int k0 = 0; k0 < 256; k0 += 32) {
        {
            int r  = t >> 3;
            int kq = (t & 7) * 4;
            int kg = k0 + kq;
            const float* src = (kg < 128) ? &h  [(row0 + r)*128 + kg]
                                          : &g_S[(row0 + r)*128 + kg - 128];
            float4 v = *(const float4*)src;
            As[kq+0][r] = v.x; As[kq+1][r] = v.y;
            As[kq+2][r] = v.z; As[kq+3][r] = v.w;
        }
#pragma unroll
        for (int n = 0; n < 2; n++) {
            int l  = t + n*256;
            int wk = l >> 4;
            int wn = (l & 15) * 4;
            int kg = k0 + wk;
            const float* src = (kg < 128) ? &Wu [kg*128 + col0 + wn]
                                          : &g_M[(kg - 128)*128 + col0 + wn];
            *(float4*)&Ws[wk][wn] = *(const float4*)src;
        }
        __syncthreads();
#pragma unroll
        for (int kk = 0; kk < 32; kk++) {
            float2 a2 = *(const float2*)&As[kk][ty*2];
            float4 b4 = *(const float4*)&Ws[kk][tx*4];
            acc[0][0] = fmaf(a2.x, b4.x, acc[0][0]);
            acc[0][1] = fmaf(a2.x, b4.y, acc[0][1]);
            acc[0][2] = fmaf(a2.x, b4.z, acc[0][2]);
            acc[0][3] = fmaf(a2.x, b4.w, acc[0][3]);
            acc[1][0] = fmaf(a2.y, b4.x, acc[1][0]);
            acc[1][1] = fmaf(a2.y, b4.y, acc[1][1]);
            acc[1][2] = fmaf(a2.y, b4.z, acc[1][2]);
            acc[1][3] = fmaf(a2.y, b4.w, acc[1][3]);
        }
        __syncthreads();
    }

    float4 vb4 = *(const float4*)&g_vb[col0 + tx*4];
#pragma unroll
    for (int r = 0; r < 2; r++) {
        int row = row0 + ty*2 + r;
        float cr = g_c[row];
        float4 v;
        v.x = fmaxf(fmaf(cr, vb4.x, acc[r][0]), 0.f);
        v.y = fmaxf(fmaf(cr, vb4.y, acc[r][1]), 0.f);
        v.z = fmaxf(fmaf(cr, vb4.z, acc[r][2]), 0.f);
        v.w = fmaxf(fmaf(cr, vb4.w, acc[r][3]), 0.f);
        *(float4*)&out[row*128 + col0 + tx*4] = v;
    }
}

// =======================================================================
extern "C" void kernel_launch(void* const* d_in, const int* in_sizes, int n_in,
                              void* d_out, int out_size)
{
    const float* h    = (const float*)d_in[0];
    const int*   adj  = (const int*)  d_in[1];
    const float* dist = (const float*)d_in[2];
    const float* Wm1  = (const float*)d_in[3];
    const float* bm1  = (const float*)d_in[4];
    const float* Wm2  = (const float*)d_in[5];
    const float* bm2  = (const float*)d_in[6];
    const float* Wa   = (const float*)d_in[7];
    const float* ba   = (const float*)d_in[8];
    const float* Wu   = (const float*)d_in[9];
    const float* bu   = (const float*)d_in[10];
    float* out = (float*)d_out;

    cudaFuncSetAttribute(k_pair, cudaFuncAttributeMaxDynamicSharedMemorySize,
                         PAIR_SMEM);

    k_stage1<<<141, 256>>>(h, Wm1, Wa, Wm2, bm2, Wu, bu);
    k_pair  <<<dim3(16, 8), 512, PAIR_SMEM>>>(dist, adj, Wm1, bm1, Wa, ba);
    k_out   <<<dim3(64, 2), 256>>>(h, Wu, out);
}